// round 11
// baseline (speedup 1.0000x reference)
#include <cuda_runtime.h>
#include <cuda_bf16.h>
#include <cstdint>

// ThermoQuantizer: groupwise abs-mean scale + softmax quantization onto a
// uniform 16-level codebook + lerp.
//
// qxn(xn) is a smooth 1-D function: each block builds a 2048-segment linear
// LUT of qxn over xn in [-12,12] (exact palindromic-Horner evaluation), then
// the hot loop is one LDS.64 + ~8 ALU/FMA per element.
//
// Round-11: cp.async.bulk (TMA-style) 4-stage smem ring pipeline. One elected
// thread streams 8KB block-tiles gmem->smem (mbarrier complete_tx) 3 stages
// ahead, and bulk-stores results smem->gmem behind. Compute warps touch ONLY
// shared memory: LDG latency (380+ cyc) leaves the warp critical path, STG
// issue cost (12cyc/STG.128) is replaced by STS + free bulk drain.
// Stage reuse protected by cp.async.bulk.wait_group.read with 1-iteration lag.
//
// Persistent single wave (152 SM x 4 blocks x 256 thr), 1 warp = 2 groups
// (half-warp per group), 8 elems/thread, packed f32x2 epilogue.

typedef unsigned long long ull;
typedef unsigned int u32;
#define FULL_MASK 0xFFFFFFFFu

#define TAB_N    2048
#define TAB_XMIN -12.0f
#define TAB_INVH (2048.0f / 24.0f)
#define TAB_OFF  1024.0f
#define TAB_UMAX 2047.999f

#define NSTAGE      4
#define TILE_BYTES  8192
#define TILE_FLOATS 2048        // 512 quads: 8 warps x 64 quads (2 groups each)

// dynamic smem layout (bytes)
#define SMO_STAGES 0
#define SMO_TAB    (NSTAGE * TILE_BYTES)          // 32768
#define SMO_MBAR   (SMO_TAB + TAB_N * 8)          // 49152
#define SMO_COEF   (SMO_MBAR + NSTAGE * 8)        // 49184 (16 x ull)
#define SMO_MISC   (SMO_COEF + 16 * 8)            // 49312 (K2, pres)
#define SMEM_TOTAL (SMO_MISC + 16)                // 49328

__device__ const float gTcol[56] = {
    0.f,-2.f, 0.f,  2.f, 0.f,-2.f, 0.f,   // j=0
    1.f, 0.f,-3.f,  0.f, 5.f, 0.f,-7.f,   // j=1
    0.f, 1.f, 0.f, -4.f, 0.f, 9.f, 0.f,   // j=2
    0.f, 0.f, 1.f,  0.f,-5.f, 0.f,14.f,   // j=3
    0.f, 0.f, 0.f,  1.f, 0.f,-6.f, 0.f,   // j=4
    0.f, 0.f, 0.f,  0.f, 1.f, 0.f,-7.f,   // j=5
    0.f, 0.f, 0.f,  0.f, 0.f, 1.f, 0.f,   // j=6
    0.f, 0.f, 0.f,  0.f, 0.f, 0.f, 1.f};  // j=7

__device__ __forceinline__ ull pk2(float lo, float hi) {
    ull r; asm("mov.b64 %0, {%1, %2};" : "=l"(r) : "f"(lo), "f"(hi)); return r;
}
__device__ __forceinline__ void upk2(ull v, float& lo, float& hi) {
    asm("mov.b64 {%0, %1}, %2;" : "=f"(lo), "=f"(hi) : "l"(v));
}
__device__ __forceinline__ ull fma2(ull a, ull b, ull c) {
    ull d; asm("fma.rn.f32x2 %0, %1, %2, %3;" : "=l"(d) : "l"(a), "l"(b), "l"(c)); return d;
}
__device__ __forceinline__ ull mul2(ull a, ull b) {
    ull d; asm("mul.rn.f32x2 %0, %1, %2;" : "=l"(d) : "l"(a), "l"(b)); return d;
}
__device__ __forceinline__ float ex2f(float a) {
    float r; asm("ex2.approx.ftz.f32 %0, %1;" : "=f"(r) : "f"(a)); return r;
}
__device__ __forceinline__ float rcpf(float a) {
    float r; asm("rcp.approx.ftz.f32 %0, %1;" : "=f"(r) : "f"(a)); return r;
}
__device__ __forceinline__ u32 smem_u32(const void* p) {
    u32 a;
    asm("{ .reg .u64 t; cvta.to.shared.u64 t, %1; cvt.u32.u64 %0, t; }"
        : "=r"(a) : "l"(p));
    return a;
}
__device__ __forceinline__ void mbar_init(u32 mb, u32 cnt) {
    asm volatile("mbarrier.init.shared.b64 [%0], %1;" :: "r"(mb), "r"(cnt) : "memory");
}
__device__ __forceinline__ void mbar_expect_tx(u32 mb, u32 bytes) {
    asm volatile("mbarrier.arrive.expect_tx.shared.b64 _, [%0], %1;"
                 :: "r"(mb), "r"(bytes) : "memory");
}
__device__ __forceinline__ void mbar_wait(u32 mb, u32 parity) {
    u32 done;
    asm volatile(
        "{\n\t.reg .pred p;\n\t"
        "mbarrier.try_wait.parity.acquire.cta.shared::cta.b64 p, [%1], %2;\n\t"
        "selp.b32 %0, 1, 0, p;\n\t}"
        : "=r"(done) : "r"(mb), "r"(parity) : "memory");
    if (!done) {
        asm volatile(
            "{\n\t.reg .pred P1;\n\t"
            "W_%=:\n\t"
            "mbarrier.try_wait.parity.acquire.cta.shared::cta.b64 P1, [%0], %1, 0x989680;\n\t"
            "@P1 bra.uni D_%=;\n\t"
            "bra.uni W_%=;\n\t"
            "D_%=:\n\t}"
            :: "r"(mb), "r"(parity) : "memory");
    }
}
__device__ __forceinline__ void bulk_ld(u32 smemDst, const float* gSrc, u32 bytes, u32 mb) {
    asm volatile(
        "cp.async.bulk.shared::cta.global.mbarrier::complete_tx::bytes [%0], [%1], %2, [%3];"
        :: "r"(smemDst), "l"(gSrc), "r"(bytes), "r"(mb) : "memory");
}
__device__ __forceinline__ void bulk_st(float* gDst, u32 smemSrc, u32 bytes) {
    asm volatile(
        "cp.async.bulk.global.shared::cta.bulk_group [%0], [%1], %2;"
        :: "l"(gDst), "r"(smemSrc), "r"(bytes) : "memory");
}

__global__ __launch_bounds__(256, 4) void ThermoQuantizer_50122268345057_kernel(
    const float* __restrict__ x,
    const float* __restrict__ cb,
    const float* __restrict__ pp,
    const float* __restrict__ pt,
    float* __restrict__ out,
    int nTotal)     // total elements
{
    extern __shared__ unsigned char sm[];
    float* stages = reinterpret_cast<float*>(sm);                 // 4 x 2048 f
    ull*   sTab   = reinterpret_cast<ull*>(sm + SMO_TAB);
    ull*   sC     = reinterpret_cast<ull*>(sm + SMO_COEF);
    float* sMisc  = reinterpret_cast<float*>(sm + SMO_MISC);
    const u32 smBase = smem_u32(sm);
    const u32 mbar0  = smBase + SMO_MBAR;

    const int tid = threadIdx.x;

    // ---- stage A: Q,S coefficient derivation (warp 0) + mbarrier init ----
    if (tid < 32) {
        const int lane0 = tid;
        const int k = lane0 & 15;
        const float invT = 1.0f / (pt[0] + 1e-6f);
        const float c = cb[k];
        const float g = __expf(-c * c * invT);
        const float Hk = g * c;

        float sg = (k & 1) ? -g : g;     // p: alternating prefix sum
        float sh = Hk;                   // m: plain prefix sum (negated)
        #pragma unroll
        for (int o = 1; o <= 8; o <<= 1) {
            float tg = __shfl_up_sync(FULL_MASK, sg, o);
            float th = __shfl_up_sync(FULL_MASK, sh, o);
            if (lane0 >= o) { sg += tg; sh += th; }
        }
        const float pv = (k & 1) ? -sg : sg;
        const float mv = -sh;

        float pb[8], mb[8];
        #pragma unroll
        for (int t = 0; t < 8; ++t) {
            pb[t] = __shfl_sync(FULL_MASK, pv, 7 + t);
            mb[t] = __shfl_sync(FULL_MASK, mv, 7 + t);
        }
        if (lane0 < 8) {
            float q = (lane0 == 0) ? pb[0] : 0.f;
            float s = (lane0 == 0) ? mb[0] : 0.f;
            const float* Tc = &gTcol[lane0 * 7];
            #pragma unroll
            for (int t = 1; t <= 7; ++t) {
                float tc = Tc[t - 1];
                q = fmaf(pb[t], tc, q);
                s = fmaf(mb[t], tc, s);
            }
            sC[lane0]     = pk2(q, q);
            sC[lane0 + 8] = pk2(s, s);
        }
        if (lane0 == 0) {
            sMisc[0] = 2.0f * (cb[1] - cb[0]) * invT * 1.4426950408889634f; // K2
            sMisc[1] = pp[0];                                               // pressure
            #pragma unroll
            for (int i = 0; i < NSTAGE; ++i) mbar_init(mbar0 + 8 * i, 1);
        }
    }
    __syncthreads();

    // ---- stage B: build qxn LUT (stage buffers double as node scratch) ----
    {
        const float* sCf = reinterpret_cast<const float*>(sC);
        const float K2 = sMisc[0];
        for (int i = tid; i <= TAB_N; i += 256) {
            float xn = TAB_XMIN + (float)i * (1.0f / TAB_INVH);
            float a = fminf(fmaxf(xn * K2, -10.0f), 10.0f);
            float r = ex2f(a);
            float z = r + rcpf(r);
            float accq = sCf[14], accs = sCf[30];
            #pragma unroll
            for (int j = 6; j >= 0; --j) {
                accq = fmaf(accq, z, sCf[2 * j]);
                accs = fmaf(accs, z, sCf[16 + 2 * j]);
            }
            float den = (r + 1.0f) * accq;
            float num = (r - 1.0f) * accs;
            stages[i] = num * rcpf(den);
        }
    }
    __syncthreads();
    for (int i = tid; i < TAB_N; i += 256)
        sTab[i] = pk2(stages[i], stages[i + 1] - stages[i]);
    __syncthreads();

    // ---- stage C: bulk-async pipeline over 8KB block-tiles ----
    const int bid = blockIdx.x, grid = gridDim.x;
    const int numBT = nTotal / TILE_FLOATS;
    const float pres  = sMisc[1];
    const float onemp = 1.0f - pres;
    const ull om2 = pk2(onemp, onemp);

    if (tid == 0) {
        #pragma unroll
        for (int j = 0; j < NSTAGE - 1; ++j) {
            long gt = (long)bid + (long)j * grid;
            if (gt < numBT) {
                u32 mb = mbar0 + 8 * j;
                mbar_expect_tx(mb, TILE_BYTES);
                bulk_ld(smBase + j * TILE_BYTES, x + gt * TILE_FLOATS, TILE_BYTES, mb);
            }
        }
    }

    const int lane = tid & 31;
    const int w = tid >> 5;
    const int h = lane >> 4;
    const int ql = lane & 15;
    const int qoff = w * 64 + h * 32 + ql;     // quad offset within 512-quad tile

    int phase = 0;
    for (int j = 0; ; ++j) {
        long gt = (long)bid + (long)j * grid;
        if (gt >= numBT) break;
        const int s = j & 3;
        mbar_wait(mbar0 + 8 * s, phase);
        if (s == 3) phase ^= 1;

        float4* st4 = reinterpret_cast<float4*>(sm + s * TILE_BYTES);
        const float4 a0 = st4[qoff];
        const float4 a1 = st4[qoff + 16];

        // group abs-mean over this 16-lane half (128 elements)
        float ss = (fabsf(a0.x) + fabsf(a0.y)) + (fabsf(a0.z) + fabsf(a0.w))
                 + (fabsf(a1.x) + fabsf(a1.y)) + (fabsf(a1.z) + fabsf(a1.w));
        ss += __shfl_xor_sync(FULL_MASK, ss, 8);
        ss += __shfl_xor_sync(FULL_MASK, ss, 4);
        ss += __shfl_xor_sync(FULL_MASK, ss, 2);
        ss += __shfl_xor_sync(FULL_MASK, ss, 1);
        const float mean_c = fmaxf(ss * (1.0f / 128.0f), 1e-5f);
        const float uScale = TAB_INVH * rcpf(mean_c);
        const float pm = pres * mean_c;
        const ull pm2 = pk2(pm, pm);

        const float xs[8] = {a0.x, a0.y, a0.z, a0.w, a1.x, a1.y, a1.z, a1.w};

        float qv[8];
        #pragma unroll
        for (int e = 0; e < 8; ++e) {
            float u = fmaf(xs[e], uScale, TAB_OFF);
            u = fminf(fmaxf(u, 0.0f), TAB_UMAX);
            int idx = (int)u;
            float frac = u - (float)idx;
            float f, d; upk2(sTab[idx], f, d);
            qv[e] = fmaf(frac, d, f);
        }

        float resv[8];
        #pragma unroll
        for (int pI = 0; pI < 4; ++pI) {
            ull xpP = pk2(xs[2 * pI], xs[2 * pI + 1]);
            ull qP  = pk2(qv[2 * pI], qv[2 * pI + 1]);
            ull resP = fma2(pm2, qP, mul2(om2, xpP));
            upk2(resP, resv[2 * pI], resv[2 * pI + 1]);
        }
        st4[qoff]      = make_float4(resv[0], resv[1], resv[2], resv[3]);
        st4[qoff + 16] = make_float4(resv[4], resv[5], resv[6], resv[7]);

        __syncthreads();    // all STS done; all reads of this stage done

        if (tid == 0) {
            asm volatile("fence.proxy.async;" ::: "memory");
            bulk_st(out + gt * TILE_FLOATS, smBase + s * TILE_BYTES, TILE_BYTES);
            asm volatile("cp.async.bulk.commit_group;" ::: "memory");
            long lt = (long)bid + (long)(j + 3) * grid;
            if (lt < numBT) {
                // stage (j+3)&3 = (j-1)&3: its store (iter j-1) must be read-
                // drained. After committing store j, <=1 outstanding => done.
                asm volatile("cp.async.bulk.wait_group.read 1;" ::: "memory");
                const int ls = (j + 3) & 3;
                u32 mb = mbar0 + 8 * ls;
                mbar_expect_tx(mb, TILE_BYTES);
                bulk_ld(smBase + ls * TILE_BYTES, x + lt * TILE_FLOATS, TILE_BYTES, mb);
            }
        }
    }
    if (tid == 0) asm volatile("cp.async.bulk.wait_group 0;" ::: "memory");

    // ---- tail (elements beyond numBT*2048; zero for 4096x4096) ----
    const long tailStart = (long)numBT * TILE_FLOATS;
    if (bid == 0 && tailStart < nTotal) {
        const int tailGroups = (int)((nTotal - tailStart) / 128);
        const float4* x4 = reinterpret_cast<const float4*>(x);
        float4* o4 = reinterpret_cast<float4*>(out);
        for (int g = w; g < tailGroups; g += 8) {       // warp per group
            long qb = tailStart / 4 + (long)g * 32 + lane;
            float4 v = x4[qb];
            float sa = fabsf(v.x) + fabsf(v.y) + fabsf(v.z) + fabsf(v.w);
            #pragma unroll
            for (int o = 16; o > 0; o >>= 1) sa += __shfl_xor_sync(FULL_MASK, sa, o);
            float mean_c = fmaxf(sa * (1.0f / 128.0f), 1e-5f);
            float uScale = TAB_INVH * rcpf(mean_c);
            float pm = pres * mean_c;
            float xv[4] = {v.x, v.y, v.z, v.w};
            float rv[4];
            #pragma unroll
            for (int e = 0; e < 4; ++e) {
                float u = fmaf(xv[e], uScale, TAB_OFF);
                u = fminf(fmaxf(u, 0.0f), TAB_UMAX);
                int idx = (int)u;
                float frac = u - (float)idx;
                float f, d; upk2(sTab[idx], f, d);
                rv[e] = fmaf(pm, fmaf(frac, d, f), onemp * xv[e]);
            }
            o4[qb] = make_float4(rv[0], rv[1], rv[2], rv[3]);
        }
    }
}

extern "C" void kernel_launch(void* const* d_in, const int* in_sizes, int n_in,
                              void* d_out, int out_size) {
    const float* x  = (const float*)d_in[0];
    const float* cbk = (const float*)d_in[1];
    const float* pr = (const float*)d_in[2];
    const float* tp = (const float*)d_in[3];
    float* out = (float*)d_out;

    static int attrSet = 0;
    if (!attrSet) {
        cudaFuncSetAttribute(ThermoQuantizer_50122268345057_kernel,
                             cudaFuncAttributeMaxDynamicSharedMemorySize, SMEM_TOTAL);
        attrSet = 1;
    }

    const int numBT = out_size / TILE_FLOATS;
    int blocks = 152 * 4;                       // one resident wave
    if (blocks > numBT) blocks = numBT;
    if (blocks < 1) blocks = 1;
    ThermoQuantizer_50122268345057_kernel<<<blocks, 256, SMEM_TOTAL>>>(
        x, cbk, pr, tp, out, out_size);
}

// round 12
// speedup vs baseline: 1.1511x; 1.1511x over previous
#include <cuda_runtime.h>
#include <cuda_bf16.h>

// ThermoQuantizer: groupwise abs-mean scale + softmax quantization onto a
// uniform 16-level codebook + lerp.
//
// qxn(xn) is a smooth 1-D function (codebook/temp fixed per launch): each
// block builds a 2048-segment linear-interp LUT of qxn over xn in [-12,12]
// via the exact palindromic-Horner evaluation; the hot loop is one LDS.64 +
// ~8 ALU/FMA per element, zero MUFU.
//
// Round-12: prefetch depth 2 (3 tiles in flight per warp) via a 3-phase
// unrolled register ring -> ~12.3KB of loads in flight per SM, covering the
// bandwidth-latency product (~10.6KB needed at 33.6 GB/s/SM, ~316ns).
// launch_bounds(256,3) gives the register headroom (84/thread).
// ld.global.cs / st.global.cs streaming (single-touch data).
//
// Persistent warp-private loop, 1 warp = 2 groups (half-warp per group),
// 8 elems/thread, packed f32x2 epilogue. No inter-warp synchronization.

typedef unsigned long long ull;
#define FULL_MASK 0xFFFFFFFFu

#define TAB_N    2048
#define TAB_XMIN -12.0f
#define TAB_INVH (2048.0f / 24.0f)
#define TAB_OFF  1024.0f
#define TAB_UMAX 2047.999f

__device__ const float gTcol[56] = {
    0.f,-2.f, 0.f,  2.f, 0.f,-2.f, 0.f,   // j=0
    1.f, 0.f,-3.f,  0.f, 5.f, 0.f,-7.f,   // j=1
    0.f, 1.f, 0.f, -4.f, 0.f, 9.f, 0.f,   // j=2
    0.f, 0.f, 1.f,  0.f,-5.f, 0.f,14.f,   // j=3
    0.f, 0.f, 0.f,  1.f, 0.f,-6.f, 0.f,   // j=4
    0.f, 0.f, 0.f,  0.f, 1.f, 0.f,-7.f,   // j=5
    0.f, 0.f, 0.f,  0.f, 0.f, 1.f, 0.f,   // j=6
    0.f, 0.f, 0.f,  0.f, 0.f, 0.f, 1.f};  // j=7

__device__ __forceinline__ ull pk2(float lo, float hi) {
    ull r; asm("mov.b64 %0, {%1, %2};" : "=l"(r) : "f"(lo), "f"(hi)); return r;
}
__device__ __forceinline__ void upk2(ull v, float& lo, float& hi) {
    asm("mov.b64 {%0, %1}, %2;" : "=f"(lo), "=f"(hi) : "l"(v));
}
__device__ __forceinline__ ull fma2(ull a, ull b, ull c) {
    ull d; asm("fma.rn.f32x2 %0, %1, %2, %3;" : "=l"(d) : "l"(a), "l"(b), "l"(c)); return d;
}
__device__ __forceinline__ ull mul2(ull a, ull b) {
    ull d; asm("mul.rn.f32x2 %0, %1, %2;" : "=l"(d) : "l"(a), "l"(b)); return d;
}
__device__ __forceinline__ float ex2f(float a) {
    float r; asm("ex2.approx.ftz.f32 %0, %1;" : "=f"(r) : "f"(a)); return r;
}
__device__ __forceinline__ float rcpf(float a) {
    float r; asm("rcp.approx.ftz.f32 %0, %1;" : "=f"(r) : "f"(a)); return r;
}
__device__ __forceinline__ float4 ldcs4(const float4* p) {
    float4 v;
    asm("ld.global.cs.v4.f32 {%0,%1,%2,%3}, [%4];"
        : "=f"(v.x), "=f"(v.y), "=f"(v.z), "=f"(v.w) : "l"(p));
    return v;
}
__device__ __forceinline__ void stcs4(float4* p, float4 v) {
    asm volatile("st.global.cs.v4.f32 [%0], {%1,%2,%3,%4};"
                 :: "l"(p), "f"(v.x), "f"(v.y), "f"(v.z), "f"(v.w) : "memory");
}

__global__ __launch_bounds__(256, 3) void ThermoQuantizer_50122268345057_kernel(
    const float* __restrict__ x,
    const float* __restrict__ cb,
    const float* __restrict__ pp,
    const float* __restrict__ pt,
    float* __restrict__ out,
    int n4)
{
    __shared__ ull   sTab[TAB_N];        // packed (f_i, f_{i+1}-f_i)
    __shared__ float sF[TAB_N + 1];      // node values (build scratch)
    __shared__ ull   sC[16];             // (q_j,q_j) j=0..7 then (s_j,s_j)
    __shared__ float sK2, sPres;

    const int tid = threadIdx.x;

    // ---- stage 1: Q,S coefficient derivation (warp 0, lane-parallel) ----
    if (tid < 32) {
        const int lane0 = tid;
        const int k = lane0 & 15;
        const float invT = 1.0f / (pt[0] + 1e-6f);
        const float c = cb[k];
        const float g = __expf(-c * c * invT);
        const float Hk = g * c;

        float sg = (k & 1) ? -g : g;     // p: alternating prefix sum
        float sh = Hk;                   // m: plain prefix sum (negated)
        #pragma unroll
        for (int o = 1; o <= 8; o <<= 1) {
            float tg = __shfl_up_sync(FULL_MASK, sg, o);
            float th = __shfl_up_sync(FULL_MASK, sh, o);
            if (lane0 >= o) { sg += tg; sh += th; }
        }
        const float pv = (k & 1) ? -sg : sg;
        const float mv = -sh;

        float pb[8], mb[8];
        #pragma unroll
        for (int t = 0; t < 8; ++t) {
            pb[t] = __shfl_sync(FULL_MASK, pv, 7 + t);
            mb[t] = __shfl_sync(FULL_MASK, mv, 7 + t);
        }
        if (lane0 < 8) {
            float q = (lane0 == 0) ? pb[0] : 0.f;
            float s = (lane0 == 0) ? mb[0] : 0.f;
            const float* Tc = &gTcol[lane0 * 7];
            #pragma unroll
            for (int t = 1; t <= 7; ++t) {
                float tc = Tc[t - 1];
                q = fmaf(pb[t], tc, q);
                s = fmaf(mb[t], tc, s);
            }
            sC[lane0]     = pk2(q, q);
            sC[lane0 + 8] = pk2(s, s);
        }
        if (lane0 == 0) {
            sK2 = 2.0f * (cb[1] - cb[0]) * invT * 1.4426950408889634f;
            sPres = pp[0];
        }
    }
    __syncthreads();

    // ---- stage 2: build qxn table (all 256 threads) ----
    {
        const float* sCf = reinterpret_cast<const float*>(sC);
        const float K2 = sK2;
        for (int i = tid; i <= TAB_N; i += 256) {
            float xn = TAB_XMIN + (float)i * (1.0f / TAB_INVH);
            float a = fminf(fmaxf(xn * K2, -10.0f), 10.0f);
            float r = ex2f(a);
            float z = r + rcpf(r);
            float accq = sCf[14], accs = sCf[30];
            #pragma unroll
            for (int j = 6; j >= 0; --j) {
                accq = fmaf(accq, z, sCf[2 * j]);
                accs = fmaf(accs, z, sCf[16 + 2 * j]);
            }
            float den = (r + 1.0f) * accq;
            float num = (r - 1.0f) * accs;
            sF[i] = num * rcpf(den);
        }
    }
    __syncthreads();
    for (int i = tid; i < TAB_N; i += 256)
        sTab[i] = pk2(sF[i], sF[i + 1] - sF[i]);
    __syncthreads();

    // ---- stage 3: persistent loop, depth-2 prefetch (3-phase ring) ----
    const int lane = tid & 31;
    const int h = lane >> 4;
    const int ql = lane & 15;
    const int warpsTotal = gridDim.x * 8;
    const int wId = blockIdx.x * 8 + (tid >> 5);
    const int numTiles = (n4 + 63) >> 6;

    const float pres = sPres;
    const float onemp = 1.0f - pres;
    const ull om2 = pk2(onemp, onemp);

    const float4* __restrict__ x4 = reinterpret_cast<const float4*>(x);
    float4* __restrict__ o4 = reinterpret_cast<float4*>(out);

    const int qrel = h * 32 + ql;   // quad offset within a 64-quad tile

    // tile load (zero-fill when out of range; groups whole-or-absent)
    #define LD_TILE(T, V0, V1)                                            \
        do {                                                              \
            int _qb = (T) * 64 + qrel;                                    \
            if ((T) < numTiles && (_qb + 16) <= n4) {                     \
                V0 = ldcs4(x4 + _qb); V1 = ldcs4(x4 + _qb + 16);          \
            } else {                                                      \
                V0 = make_float4(0.f, 0.f, 0.f, 0.f); V1 = V0;            \
            }                                                             \
        } while (0)

    #define COMPUTE_STORE(T, V0, V1)                                      \
        do {                                                              \
            float ss = (fabsf(V0.x) + fabsf(V0.y)) + (fabsf(V0.z) + fabsf(V0.w)) \
                     + (fabsf(V1.x) + fabsf(V1.y)) + (fabsf(V1.z) + fabsf(V1.w)); \
            ss += __shfl_xor_sync(FULL_MASK, ss, 8);                      \
            ss += __shfl_xor_sync(FULL_MASK, ss, 4);                      \
            ss += __shfl_xor_sync(FULL_MASK, ss, 2);                      \
            ss += __shfl_xor_sync(FULL_MASK, ss, 1);                      \
            const float mean_c = fmaxf(ss * (1.0f / 128.0f), 1e-5f);      \
            const float uScale = TAB_INVH * rcpf(mean_c);                 \
            const float pm = pres * mean_c;                               \
            const ull pm2 = pk2(pm, pm);                                  \
            const float xs[8] = {V0.x, V0.y, V0.z, V0.w, V1.x, V1.y, V1.z, V1.w}; \
            float qv[8];                                                  \
            _Pragma("unroll")                                             \
            for (int e = 0; e < 8; ++e) {                                 \
                float u = fmaf(xs[e], uScale, TAB_OFF);                   \
                u = fminf(fmaxf(u, 0.0f), TAB_UMAX);                      \
                int idx = (int)u;                                         \
                float frac = u - (float)idx;                              \
                float f, d; upk2(sTab[idx], f, d);                        \
                qv[e] = fmaf(frac, d, f);                                 \
            }                                                             \
            int _qb = (T) * 64 + qrel;                                    \
            if ((_qb + 16) <= n4) {                                       \
                float resv[8];                                            \
                _Pragma("unroll")                                         \
                for (int pI = 0; pI < 4; ++pI) {                          \
                    ull xpP = pk2(xs[2 * pI], xs[2 * pI + 1]);            \
                    ull qP  = pk2(qv[2 * pI], qv[2 * pI + 1]);            \
                    ull resP = fma2(pm2, qP, mul2(om2, xpP));             \
                    upk2(resP, resv[2 * pI], resv[2 * pI + 1]);           \
                }                                                         \
                stcs4(o4 + _qb,      make_float4(resv[0], resv[1], resv[2], resv[3])); \
                stcs4(o4 + _qb + 16, make_float4(resv[4], resv[5], resv[6], resv[7])); \
            }                                                             \
        } while (0)

    float4 A0, A1, B0, B1, C0, C1;
    int t = wId;
    const int W = warpsTotal;
    LD_TILE(t, A0, A1);
    LD_TILE(t + W, B0, B1);

    #pragma unroll 1
    while (true) {
        if (t >= numTiles) break;
        LD_TILE(t + 2 * W, C0, C1);
        COMPUTE_STORE(t, A0, A1);

        if (t + W >= numTiles) break;
        LD_TILE(t + 3 * W, A0, A1);
        COMPUTE_STORE(t + W, B0, B1);

        if (t + 2 * W >= numTiles) break;
        LD_TILE(t + 4 * W, B0, B1);
        COMPUTE_STORE(t + 2 * W, C0, C1);

        t += 3 * W;
    }

    #undef LD_TILE
    #undef COMPUTE_STORE
}

extern "C" void kernel_launch(void* const* d_in, const int* in_sizes, int n_in,
                              void* d_out, int out_size) {
    const float* x  = (const float*)d_in[0];
    const float* cbk = (const float*)d_in[1];
    const float* pr = (const float*)d_in[2];
    const float* tp = (const float*)d_in[3];
    float* out = (float*)d_out;

    const int n4 = out_size / 4;               // float4 quads
    const int numTiles = (n4 + 63) >> 6;
    int blocks = 152 * 3;                      // one resident wave at 3 blocks/SM
    const int maxBlocks = (numTiles + 7) / 8;  // 8 warps/block
    if (blocks > maxBlocks) blocks = maxBlocks;
    if (blocks < 1) blocks = 1;
    ThermoQuantizer_50122268345057_kernel<<<blocks, 256>>>(x, cbk, pr, tp, out, n4);
}

// round 13
// speedup vs baseline: 1.2326x; 1.0708x over previous
#include <cuda_runtime.h>
#include <cuda_bf16.h>
#include <cuda_fp16.h>

// ThermoQuantizer: groupwise abs-mean scale + softmax quantization onto a
// uniform 16-level codebook + lerp.
//
// qxn(xn) is a smooth 1-D function (codebook/temp fixed per launch): each
// block builds a 2048-segment linear-interp LUT of qxn over xn in [-12,12]
// via the exact palindromic-Horner evaluation.
//
// Round-13: attack the L1TEX bottleneck (63-66% busy in all LUT variants —
// highest counter anywhere this session; LDS conflicts + STG issue dominate):
//   - LUT entries packed (f, delta) as __half2 -> LDS.32 lookup: halves LDS
//     bytes and conflict phases; +2 cvt/element on the idle FMA pipe.
//     fp16 quantization of qxn (|qxn|<=1) -> output err ~1.3e-4 << 1e-3 gate.
//   - plain (evict-normal) loads: x is re-read every graph replay and fits in
//     L2; .cs was discarding reusable lines. Stores keep .cs (write-once).
//   - R10 frame: depth-1 register prefetch, launch_bounds(256,4), persistent.
//
// 1 warp = 2 groups (half-warp per group), 8 elems/thread, f32x2 epilogue.

typedef unsigned long long ull;
#define FULL_MASK 0xFFFFFFFFu

#define TAB_N    2048
#define TAB_XMIN -12.0f
#define TAB_INVH (2048.0f / 24.0f)
#define TAB_OFF  1024.0f
#define TAB_UMAX 2047.999f

__device__ const float gTcol[56] = {
    0.f,-2.f, 0.f,  2.f, 0.f,-2.f, 0.f,   // j=0
    1.f, 0.f,-3.f,  0.f, 5.f, 0.f,-7.f,   // j=1
    0.f, 1.f, 0.f, -4.f, 0.f, 9.f, 0.f,   // j=2
    0.f, 0.f, 1.f,  0.f,-5.f, 0.f,14.f,   // j=3
    0.f, 0.f, 0.f,  1.f, 0.f,-6.f, 0.f,   // j=4
    0.f, 0.f, 0.f,  0.f, 1.f, 0.f,-7.f,   // j=5
    0.f, 0.f, 0.f,  0.f, 0.f, 1.f, 0.f,   // j=6
    0.f, 0.f, 0.f,  0.f, 0.f, 0.f, 1.f};  // j=7

__device__ __forceinline__ ull pk2(float lo, float hi) {
    ull r; asm("mov.b64 %0, {%1, %2};" : "=l"(r) : "f"(lo), "f"(hi)); return r;
}
__device__ __forceinline__ void upk2(ull v, float& lo, float& hi) {
    asm("mov.b64 {%0, %1}, %2;" : "=f"(lo), "=f"(hi) : "l"(v));
}
__device__ __forceinline__ ull fma2(ull a, ull b, ull c) {
    ull d; asm("fma.rn.f32x2 %0, %1, %2, %3;" : "=l"(d) : "l"(a), "l"(b), "l"(c)); return d;
}
__device__ __forceinline__ ull mul2(ull a, ull b) {
    ull d; asm("mul.rn.f32x2 %0, %1, %2;" : "=l"(d) : "l"(a), "l"(b)); return d;
}
__device__ __forceinline__ float ex2f(float a) {
    float r; asm("ex2.approx.ftz.f32 %0, %1;" : "=f"(r) : "f"(a)); return r;
}
__device__ __forceinline__ float rcpf(float a) {
    float r; asm("rcp.approx.ftz.f32 %0, %1;" : "=f"(r) : "f"(a)); return r;
}
__device__ __forceinline__ void stcs4(float4* p, float4 v) {
    asm volatile("st.global.cs.v4.f32 [%0], {%1,%2,%3,%4};"
                 :: "l"(p), "f"(v.x), "f"(v.y), "f"(v.z), "f"(v.w) : "memory");
}

__global__ __launch_bounds__(256, 4) void ThermoQuantizer_50122268345057_kernel(
    const float* __restrict__ x,
    const float* __restrict__ cb,
    const float* __restrict__ pp,
    const float* __restrict__ pt,
    float* __restrict__ out,
    int n4)
{
    __shared__ __half2 sTabH[TAB_N];     // packed fp16 (f_i, f_{i+1}-f_i)
    __shared__ float sF[TAB_N + 1];      // node values (build scratch, fp32)
    __shared__ ull   sC[16];             // (q_j,q_j) j=0..7 then (s_j,s_j)
    __shared__ float sK2, sPres;

    const int tid = threadIdx.x;

    // ---- stage 1: Q,S coefficient derivation (warp 0, lane-parallel) ----
    if (tid < 32) {
        const int lane0 = tid;
        const int k = lane0 & 15;
        const float invT = 1.0f / (pt[0] + 1e-6f);
        const float c = cb[k];
        const float g = __expf(-c * c * invT);
        const float Hk = g * c;

        float sg = (k & 1) ? -g : g;     // p: alternating prefix sum
        float sh = Hk;                   // m: plain prefix sum (negated)
        #pragma unroll
        for (int o = 1; o <= 8; o <<= 1) {
            float tg = __shfl_up_sync(FULL_MASK, sg, o);
            float th = __shfl_up_sync(FULL_MASK, sh, o);
            if (lane0 >= o) { sg += tg; sh += th; }
        }
        const float pv = (k & 1) ? -sg : sg;
        const float mv = -sh;

        float pb[8], mb[8];
        #pragma unroll
        for (int t = 0; t < 8; ++t) {
            pb[t] = __shfl_sync(FULL_MASK, pv, 7 + t);
            mb[t] = __shfl_sync(FULL_MASK, mv, 7 + t);
        }
        if (lane0 < 8) {
            float q = (lane0 == 0) ? pb[0] : 0.f;
            float s = (lane0 == 0) ? mb[0] : 0.f;
            const float* Tc = &gTcol[lane0 * 7];
            #pragma unroll
            for (int t = 1; t <= 7; ++t) {
                float tc = Tc[t - 1];
                q = fmaf(pb[t], tc, q);
                s = fmaf(mb[t], tc, s);
            }
            sC[lane0]     = pk2(q, q);
            sC[lane0 + 8] = pk2(s, s);
        }
        if (lane0 == 0) {
            sK2 = 2.0f * (cb[1] - cb[0]) * invT * 1.4426950408889634f;
            sPres = pp[0];
        }
    }
    __syncthreads();

    // ---- stage 2: build qxn table (all 256 threads), pack to fp16x2 ----
    {
        const float* sCf = reinterpret_cast<const float*>(sC);
        const float K2 = sK2;
        for (int i = tid; i <= TAB_N; i += 256) {
            float xn = TAB_XMIN + (float)i * (1.0f / TAB_INVH);
            float a = fminf(fmaxf(xn * K2, -10.0f), 10.0f);
            float r = ex2f(a);
            float z = r + rcpf(r);
            float accq = sCf[14], accs = sCf[30];
            #pragma unroll
            for (int j = 6; j >= 0; --j) {
                accq = fmaf(accq, z, sCf[2 * j]);
                accs = fmaf(accs, z, sCf[16 + 2 * j]);
            }
            float den = (r + 1.0f) * accq;
            float num = (r - 1.0f) * accs;
            sF[i] = num * rcpf(den);
        }
    }
    __syncthreads();
    for (int i = tid; i < TAB_N; i += 256)
        sTabH[i] = __floats2half2_rn(sF[i], sF[i + 1] - sF[i]);
    __syncthreads();

    // ---- stage 3: persistent loop, depth-1 register prefetch ----
    const int lane = tid & 31;
    const int h = lane >> 4;
    const int ql = lane & 15;
    const int warpsTotal = gridDim.x * 8;
    const int wId = blockIdx.x * 8 + (tid >> 5);
    const int numTiles = (n4 + 63) >> 6;

    const float pres = sPres;
    const float onemp = 1.0f - pres;
    const ull om2 = pk2(onemp, onemp);

    const float4* __restrict__ x4 = reinterpret_cast<const float4*>(x);
    float4* __restrict__ o4 = reinterpret_cast<float4*>(out);

    int tile = wId;
    bool vld = tile < numTiles;
    int qb = tile * 64 + h * 32 + ql;
    float4 a0 = make_float4(0.f, 0.f, 0.f, 0.f), a1 = a0;
    if (vld && (qb + 16) <= n4) { a0 = x4[qb]; a1 = x4[qb + 16]; }

    #pragma unroll 1
    while (vld) {
        // prefetch next tile before touching current data
        const int ntile = tile + warpsTotal;
        const bool nvld = ntile < numTiles;
        int nqb = 0;
        float4 b0 = make_float4(0.f, 0.f, 0.f, 0.f), b1 = b0;
        if (nvld) {
            nqb = ntile * 64 + h * 32 + ql;
            if ((nqb + 16) <= n4) { b0 = x4[nqb]; b1 = x4[nqb + 16]; }
        }

        // group abs-mean over this 16-lane half (128 elements)
        float ss = (fabsf(a0.x) + fabsf(a0.y)) + (fabsf(a0.z) + fabsf(a0.w))
                 + (fabsf(a1.x) + fabsf(a1.y)) + (fabsf(a1.z) + fabsf(a1.w));
        ss += __shfl_xor_sync(FULL_MASK, ss, 8);
        ss += __shfl_xor_sync(FULL_MASK, ss, 4);
        ss += __shfl_xor_sync(FULL_MASK, ss, 2);
        ss += __shfl_xor_sync(FULL_MASK, ss, 1);
        const float mean_c = fmaxf(ss * (1.0f / 128.0f), 1e-5f);
        const float uScale = TAB_INVH * rcpf(mean_c);
        const float pm = pres * mean_c;
        const ull pm2 = pk2(pm, pm);

        const float xs[8] = {a0.x, a0.y, a0.z, a0.w, a1.x, a1.y, a1.z, a1.w};

        float qv[8];
        #pragma unroll
        for (int e = 0; e < 8; ++e) {
            float u = fmaf(xs[e], uScale, TAB_OFF);
            u = fminf(fmaxf(u, 0.0f), TAB_UMAX);
            int idx = (int)u;
            float frac = u - (float)idx;
            float2 fd = __half22float2(sTabH[idx]);   // LDS.32 + 2 cvt
            qv[e] = fmaf(frac, fd.y, fd.x);
        }

        if ((qb + 16) <= n4) {
            float resv[8];
            #pragma unroll
            for (int pI = 0; pI < 4; ++pI) {
                ull xpP = pk2(xs[2 * pI], xs[2 * pI + 1]);
                ull qP  = pk2(qv[2 * pI], qv[2 * pI + 1]);
                ull resP = fma2(pm2, qP, mul2(om2, xpP));
                upk2(resP, resv[2 * pI], resv[2 * pI + 1]);
            }
            stcs4(o4 + qb,      make_float4(resv[0], resv[1], resv[2], resv[3]));
            stcs4(o4 + qb + 16, make_float4(resv[4], resv[5], resv[6], resv[7]));
        }

        tile = ntile; qb = nqb; vld = nvld; a0 = b0; a1 = b1;
    }
}

extern "C" void kernel_launch(void* const* d_in, const int* in_sizes, int n_in,
                              void* d_out, int out_size) {
    const float* x  = (const float*)d_in[0];
    const float* cbk = (const float*)d_in[1];
    const float* pr = (const float*)d_in[2];
    const float* tp = (const float*)d_in[3];
    float* out = (float*)d_out;

    const int n4 = out_size / 4;               // float4 quads
    const int numTiles = (n4 + 63) >> 6;
    int blocks = 152 * 4;                      // one resident wave at 4 blocks/SM
    const int maxBlocks = (numTiles + 7) / 8;  // 8 warps/block
    if (blocks > maxBlocks) blocks = maxBlocks;
    if (blocks < 1) blocks = 1;
    ThermoQuantizer_50122268345057_kernel<<<blocks, 256>>>(x, cbk, pr, tp, out, n4);
}

// round 14
// speedup vs baseline: 1.2468x; 1.0115x over previous
#include <cuda_runtime.h>
#include <cuda_bf16.h>
#include <cuda_fp16.h>

// ThermoQuantizer: groupwise abs-mean scale + softmax quantization onto a
// uniform 16-level codebook + lerp.
//
// qxn(xn) is a smooth 1-D function (codebook/temp fixed per launch): each
// block builds a 2048-segment linear-interp LUT of qxn over xn in [-12,12]
// via the exact palindromic-Horner evaluation.
//
// R13 (win): fp16x2 LUT entries -> LDS.32 lookups (halved L1TEX/LDS cost),
// default-policy loads (x fits in L2 across graph replays), .cs stores.
// Round-14: single change -> launch_bounds(256,5), grid 152x5: 40 warps/SM.
// Issue was 57% at 32 warps with L1TEX no longer the obstruction; buy the
// last latency coverage with warps (ptxas rematerializes ~6 regs, no spill).
//
// 1 warp = 2 groups (half-warp per group), 8 elems/thread, f32x2 epilogue,
// depth-1 register prefetch, persistent single wave.

typedef unsigned long long ull;
#define FULL_MASK 0xFFFFFFFFu

#define TAB_N    2048
#define TAB_XMIN -12.0f
#define TAB_INVH (2048.0f / 24.0f)
#define TAB_OFF  1024.0f
#define TAB_UMAX 2047.999f

__device__ const float gTcol[56] = {
    0.f,-2.f, 0.f,  2.f, 0.f,-2.f, 0.f,   // j=0
    1.f, 0.f,-3.f,  0.f, 5.f, 0.f,-7.f,   // j=1
    0.f, 1.f, 0.f, -4.f, 0.f, 9.f, 0.f,   // j=2
    0.f, 0.f, 1.f,  0.f,-5.f, 0.f,14.f,   // j=3
    0.f, 0.f, 0.f,  1.f, 0.f,-6.f, 0.f,   // j=4
    0.f, 0.f, 0.f,  0.f, 1.f, 0.f,-7.f,   // j=5
    0.f, 0.f, 0.f,  0.f, 0.f, 1.f, 0.f,   // j=6
    0.f, 0.f, 0.f,  0.f, 0.f, 0.f, 1.f};  // j=7

__device__ __forceinline__ ull pk2(float lo, float hi) {
    ull r; asm("mov.b64 %0, {%1, %2};" : "=l"(r) : "f"(lo), "f"(hi)); return r;
}
__device__ __forceinline__ void upk2(ull v, float& lo, float& hi) {
    asm("mov.b64 {%0, %1}, %2;" : "=f"(lo), "=f"(hi) : "l"(v));
}
__device__ __forceinline__ ull fma2(ull a, ull b, ull c) {
    ull d; asm("fma.rn.f32x2 %0, %1, %2, %3;" : "=l"(d) : "l"(a), "l"(b), "l"(c)); return d;
}
__device__ __forceinline__ ull mul2(ull a, ull b) {
    ull d; asm("mul.rn.f32x2 %0, %1, %2;" : "=l"(d) : "l"(a), "l"(b)); return d;
}
__device__ __forceinline__ float ex2f(float a) {
    float r; asm("ex2.approx.ftz.f32 %0, %1;" : "=f"(r) : "f"(a)); return r;
}
__device__ __forceinline__ float rcpf(float a) {
    float r; asm("rcp.approx.ftz.f32 %0, %1;" : "=f"(r) : "f"(a)); return r;
}
__device__ __forceinline__ void stcs4(float4* p, float4 v) {
    asm volatile("st.global.cs.v4.f32 [%0], {%1,%2,%3,%4};"
                 :: "l"(p), "f"(v.x), "f"(v.y), "f"(v.z), "f"(v.w) : "memory");
}

__global__ __launch_bounds__(256, 5) void ThermoQuantizer_50122268345057_kernel(
    const float* __restrict__ x,
    const float* __restrict__ cb,
    const float* __restrict__ pp,
    const float* __restrict__ pt,
    float* __restrict__ out,
    int n4)
{
    __shared__ __half2 sTabH[TAB_N];     // packed fp16 (f_i, f_{i+1}-f_i)
    __shared__ float sF[TAB_N + 1];      // node values (build scratch, fp32)
    __shared__ ull   sC[16];             // (q_j,q_j) j=0..7 then (s_j,s_j)
    __shared__ float sK2, sPres;

    const int tid = threadIdx.x;

    // ---- stage 1: Q,S coefficient derivation (warp 0, lane-parallel) ----
    if (tid < 32) {
        const int lane0 = tid;
        const int k = lane0 & 15;
        const float invT = 1.0f / (pt[0] + 1e-6f);
        const float c = cb[k];
        const float g = __expf(-c * c * invT);
        const float Hk = g * c;

        float sg = (k & 1) ? -g : g;     // p: alternating prefix sum
        float sh = Hk;                   // m: plain prefix sum (negated)
        #pragma unroll
        for (int o = 1; o <= 8; o <<= 1) {
            float tg = __shfl_up_sync(FULL_MASK, sg, o);
            float th = __shfl_up_sync(FULL_MASK, sh, o);
            if (lane0 >= o) { sg += tg; sh += th; }
        }
        const float pv = (k & 1) ? -sg : sg;
        const float mv = -sh;

        float pb[8], mb[8];
        #pragma unroll
        for (int t = 0; t < 8; ++t) {
            pb[t] = __shfl_sync(FULL_MASK, pv, 7 + t);
            mb[t] = __shfl_sync(FULL_MASK, mv, 7 + t);
        }
        if (lane0 < 8) {
            float q = (lane0 == 0) ? pb[0] : 0.f;
            float s = (lane0 == 0) ? mb[0] : 0.f;
            const float* Tc = &gTcol[lane0 * 7];
            #pragma unroll
            for (int t = 1; t <= 7; ++t) {
                float tc = Tc[t - 1];
                q = fmaf(pb[t], tc, q);
                s = fmaf(mb[t], tc, s);
            }
            sC[lane0]     = pk2(q, q);
            sC[lane0 + 8] = pk2(s, s);
        }
        if (lane0 == 0) {
            sK2 = 2.0f * (cb[1] - cb[0]) * invT * 1.4426950408889634f;
            sPres = pp[0];
        }
    }
    __syncthreads();

    // ---- stage 2: build qxn table (all 256 threads), pack to fp16x2 ----
    {
        const float* sCf = reinterpret_cast<const float*>(sC);
        const float K2 = sK2;
        for (int i = tid; i <= TAB_N; i += 256) {
            float xn = TAB_XMIN + (float)i * (1.0f / TAB_INVH);
            float a = fminf(fmaxf(xn * K2, -10.0f), 10.0f);
            float r = ex2f(a);
            float z = r + rcpf(r);
            float accq = sCf[14], accs = sCf[30];
            #pragma unroll
            for (int j = 6; j >= 0; --j) {
                accq = fmaf(accq, z, sCf[2 * j]);
                accs = fmaf(accs, z, sCf[16 + 2 * j]);
            }
            float den = (r + 1.0f) * accq;
            float num = (r - 1.0f) * accs;
            sF[i] = num * rcpf(den);
        }
    }
    __syncthreads();
    for (int i = tid; i < TAB_N; i += 256)
        sTabH[i] = __floats2half2_rn(sF[i], sF[i + 1] - sF[i]);
    __syncthreads();

    // ---- stage 3: persistent loop, depth-1 register prefetch ----
    const int lane = tid & 31;
    const int h = lane >> 4;
    const int ql = lane & 15;
    const int warpsTotal = gridDim.x * 8;
    const int wId = blockIdx.x * 8 + (tid >> 5);
    const int numTiles = (n4 + 63) >> 6;

    const float pres = sPres;
    const float onemp = 1.0f - pres;
    const ull om2 = pk2(onemp, onemp);

    const float4* __restrict__ x4 = reinterpret_cast<const float4*>(x);
    float4* __restrict__ o4 = reinterpret_cast<float4*>(out);

    int tile = wId;
    bool vld = tile < numTiles;
    int qb = tile * 64 + h * 32 + ql;
    float4 a0 = make_float4(0.f, 0.f, 0.f, 0.f), a1 = a0;
    if (vld && (qb + 16) <= n4) { a0 = x4[qb]; a1 = x4[qb + 16]; }

    #pragma unroll 1
    while (vld) {
        // prefetch next tile before touching current data
        const int ntile = tile + warpsTotal;
        const bool nvld = ntile < numTiles;
        int nqb = 0;
        float4 b0 = make_float4(0.f, 0.f, 0.f, 0.f), b1 = b0;
        if (nvld) {
            nqb = ntile * 64 + h * 32 + ql;
            if ((nqb + 16) <= n4) { b0 = x4[nqb]; b1 = x4[nqb + 16]; }
        }

        // group abs-mean over this 16-lane half (128 elements)
        float ss = (fabsf(a0.x) + fabsf(a0.y)) + (fabsf(a0.z) + fabsf(a0.w))
                 + (fabsf(a1.x) + fabsf(a1.y)) + (fabsf(a1.z) + fabsf(a1.w));
        ss += __shfl_xor_sync(FULL_MASK, ss, 8);
        ss += __shfl_xor_sync(FULL_MASK, ss, 4);
        ss += __shfl_xor_sync(FULL_MASK, ss, 2);
        ss += __shfl_xor_sync(FULL_MASK, ss, 1);
        const float mean_c = fmaxf(ss * (1.0f / 128.0f), 1e-5f);
        const float uScale = TAB_INVH * rcpf(mean_c);
        const float pm = pres * mean_c;
        const ull pm2 = pk2(pm, pm);

        const float xs[8] = {a0.x, a0.y, a0.z, a0.w, a1.x, a1.y, a1.z, a1.w};

        float qv[8];
        #pragma unroll
        for (int e = 0; e < 8; ++e) {
            float u = fmaf(xs[e], uScale, TAB_OFF);
            u = fminf(fmaxf(u, 0.0f), TAB_UMAX);
            int idx = (int)u;
            float frac = u - (float)idx;
            float2 fd = __half22float2(sTabH[idx]);   // LDS.32 + 2 cvt
            qv[e] = fmaf(frac, fd.y, fd.x);
        }

        if ((qb + 16) <= n4) {
            float resv[8];
            #pragma unroll
            for (int pI = 0; pI < 4; ++pI) {
                ull xpP = pk2(xs[2 * pI], xs[2 * pI + 1]);
                ull qP  = pk2(qv[2 * pI], qv[2 * pI + 1]);
                ull resP = fma2(pm2, qP, mul2(om2, xpP));
                upk2(resP, resv[2 * pI], resv[2 * pI + 1]);
            }
            stcs4(o4 + qb,      make_float4(resv[0], resv[1], resv[2], resv[3]));
            stcs4(o4 + qb + 16, make_float4(resv[4], resv[5], resv[6], resv[7]));
        }

        tile = ntile; qb = nqb; vld = nvld; a0 = b0; a1 = b1;
    }
}

extern "C" void kernel_launch(void* const* d_in, const int* in_sizes, int n_in,
                              void* d_out, int out_size) {
    const float* x  = (const float*)d_in[0];
    const float* cbk = (const float*)d_in[1];
    const float* pr = (const float*)d_in[2];
    const float* tp = (const float*)d_in[3];
    float* out = (float*)d_out;

    const int n4 = out_size / 4;               // float4 quads
    const int numTiles = (n4 + 63) >> 6;
    int blocks = 152 * 5;                      // one resident wave at 5 blocks/SM
    const int maxBlocks = (numTiles + 7) / 8;  // 8 warps/block
    if (blocks > maxBlocks) blocks = maxBlocks;
    if (blocks < 1) blocks = 1;
    ThermoQuantizer_50122268345057_kernel<<<blocks, 256>>>(x, cbk, pr, tp, out, n4);
}